// round 13
// baseline (speedup 1.0000x reference)
#include <cuda_runtime.h>
#include <cuda_bf16.h>
#include <math.h>
#include <float.h>

// Problem shape (LG_MGC_2731599200834): B=256, L=576, D=1024, k=24
#define D_DIM  1024
#define NVEC   (D_DIM / 4)        // 256 float4 per row
#define MAX_B  256
#define MAX_L  576
#define MAX_K  64
#define DSPLIT 4                  // gather kernel splits each row into 4 chunks

// Scratch (device globals; no allocation allowed).
__device__ float        g_sims[MAX_B * MAX_L];
__device__ int          g_topk[MAX_B * MAX_K];
__device__ unsigned int g_count[MAX_B];          // zero-init; self-resetting

// ---------------------------------------------------------------------------
// Kernel A: streaming sims pass (604 MB, DRAM-bound; R3-measured 91.5us @84%)
// + last-block-per-batch selection epilogue (overlapped under the stream).
//
// grid = (ceil(L/8), B), block = 256 (8 warps), one warp per token.
// Ranking by dot * rsqrt(|t|^2) is order-equivalent to the reference cosine
// (n_i is a positive per-batch scalar; eps clamp inactive at these scales).
//
// Epilogue: each block fences its g_sims writes and bumps g_count[b]; the
// last of the 72 blocks for batch b computes the rank-based bottom-k ONCE
// (top_k-stable ties, collision-free compaction into g_topk) and resets the
// counter for the next graph replay.
// ---------------------------------------------------------------------------
__global__ void __launch_bounds__(256)
sims_select_kernel(const float* __restrict__ i_feats,
                   const float* __restrict__ image_feats,
                   const int* __restrict__ k_ptr,
                   int L)
{
    __shared__ float4   s_i[NVEC];     // 4 KB: i_feats row
    __shared__ float    s_v[MAX_L];    // 2.3 KB: sims (epilogue only)
    __shared__ unsigned s_ticket;

    const int b    = blockIdx.y;
    const int tid  = threadIdx.x;
    const int warp = tid >> 5;
    const int lane = tid & 31;

    s_i[tid] = reinterpret_cast<const float4*>(i_feats + (size_t)b * D_DIM)[tid];
    __syncthreads();

    const int token = blockIdx.x * 8 + warp;
    if (token < L) {
        const float4* __restrict__ tok = reinterpret_cast<const float4*>(
            image_feats + ((size_t)b * L + token) * D_DIM) + lane;

        float dot = 0.f, nt2 = 0.f;
        #pragma unroll
        for (int j = 0; j < NVEC / 32; ++j) {         // 8 iterations
            float4 v = __ldg(tok + j * 32);           // coalesced 128B/warp/step
            float4 a = s_i[lane + j * 32];
            dot += a.x * v.x + a.y * v.y + a.z * v.z + a.w * v.w;
            nt2 += v.x * v.x + v.y * v.y + v.z * v.z + v.w * v.w;
        }
        #pragma unroll
        for (int off = 16; off > 0; off >>= 1) {
            dot += __shfl_xor_sync(0xffffffffu, dot, off);
            nt2 += __shfl_xor_sync(0xffffffffu, nt2, off);
        }
        if (lane == 0) {
            g_sims[b * L + token] = dot * rsqrtf(fmaxf(nt2, 1e-16f));
            __threadfence();                          // publish before ticket
        }
    }
    __syncthreads();

    if (tid == 0)
        s_ticket = atomicAdd(&g_count[b], 1u);
    __syncthreads();

    if (s_ticket != gridDim.x - 1)                    // not the last block
        return;

    // ---- selection epilogue (one block per batch) ----
    __threadfence();                                  // see peers' g_sims

    int k = *k_ptr;
    if (k < 1) k = 1;
    if (k > MAX_K) k = MAX_K;

    for (int i = tid; i < L; i += 256)
        s_v[i] = g_sims[b * L + i];
    __syncthreads();

    // rank(i) = #{ j : v_j < v_i || (v_j == v_i && j < i) }; rank < k selects
    // the k smallest with top_k-stable tie-break.
    for (int i = tid; i < L; i += 256) {
        const float v = s_v[i];
        int rank = 0;
        #pragma unroll 8
        for (int j = 0; j < MAX_L; ++j) {
            float w = s_v[j];                         // LDS broadcast
            rank += (w < v) | ((w == v) & (j < i));
        }
        if (rank < k)
            g_topk[b * MAX_K + rank] = i;
    }
    __syncthreads();

    if (tid == 0)
        g_count[b] = 0;                               // reset for next replay
}

// ---------------------------------------------------------------------------
// Kernel G: pure gather-mean. grid = (DSPLIT, B) = 1024 blocks x 256 threads.
// tg = tid/64 sums tokens tg, tg+4, ... over its 64-float4 chunk (6 indep.
// coalesced loads per thread); partials reduced in smem; tg 0 writes.
// ---------------------------------------------------------------------------
__global__ void __launch_bounds__(256)
gather_mean_kernel(const float* __restrict__ image_feats,
                   const int* __restrict__ k_ptr,
                   float* __restrict__ out,
                   int L)
{
    __shared__ int    s_idx[MAX_K];
    __shared__ float4 s_part[256];

    const int split = blockIdx.x;
    const int b     = blockIdx.y;
    const int tid   = threadIdx.x;

    int k = *k_ptr;
    if (k < 1) k = 1;
    if (k > MAX_K) k = MAX_K;

    if (tid < k)
        s_idx[tid] = g_topk[b * MAX_K + tid];
    __syncthreads();

    const int tg    = tid >> 6;          // 0..3
    const int slot  = tid & 63;
    const int gslot = split * 64 + slot;

    const float4* __restrict__ rowbase = reinterpret_cast<const float4*>(
        image_feats + (size_t)b * L * D_DIM);

    float4 acc = make_float4(0.f, 0.f, 0.f, 0.f);
    #pragma unroll 6
    for (int j = tg; j < k; j += 4) {
        float4 v = __ldg(rowbase + (size_t)s_idx[j] * NVEC + gslot);
        acc.x += v.x; acc.y += v.y; acc.z += v.z; acc.w += v.w;
    }
    s_part[tid] = acc;
    __syncthreads();

    if (tg == 0) {
        float4 a0 = s_part[slot];
        float4 a1 = s_part[64 + slot];
        float4 a2 = s_part[128 + slot];
        float4 a3 = s_part[192 + slot];
        const float inv_k = 1.0f / (float)k;
        float4 r;
        r.x = (a0.x + a1.x + a2.x + a3.x) * inv_k;
        r.y = (a0.y + a1.y + a2.y + a3.y) * inv_k;
        r.z = (a0.z + a1.z + a2.z + a3.z) * inv_k;
        r.w = (a0.w + a1.w + a2.w + a3.w) * inv_k;
        reinterpret_cast<float4*>(out + (size_t)b * D_DIM)[gslot] = r;
    }
}

// ---------------------------------------------------------------------------
extern "C" void kernel_launch(void* const* d_in, const int* in_sizes, int n_in,
                              void* d_out, int out_size)
{
    const float* i_feats     = (const float*)d_in[0];   // [B, D]
    const float* image_feats = (const float*)d_in[1];   // [B, L, D]
    const int*   k_ptr       = (const int*)d_in[2];     // scalar k

    const int B = in_sizes[0] / D_DIM;                  // 256
    const int L = in_sizes[1] / in_sizes[0];            // 576

    dim3 gridA((L + 7) / 8, B);
    sims_select_kernel<<<gridA, 256>>>(i_feats, image_feats, k_ptr, L);

    dim3 gridG(DSPLIT, B);
    gather_mean_kernel<<<gridG, 256>>>(image_feats, k_ptr, (float*)d_out, L);
}

// round 14
// speedup vs baseline: 1.9029x; 1.9029x over previous
#include <cuda_runtime.h>
#include <cuda_bf16.h>
#include <math.h>
#include <float.h>

// Problem shape (LG_MGC_2731599200834): B=256, L=576, D=1024, k=24
#define D_DIM  1024
#define NVEC   (D_DIM / 4)        // 256 float4 per row
#define MAX_B  256
#define MAX_L  576
#define MAX_K  64
#define NBINS  512
#define TPB_T  576                // tail kernel threads (18 warps)

// Scratch (device global; no allocation allowed).
__device__ float g_sims[MAX_B * MAX_L];

// ---------------------------------------------------------------------------
// Kernel A: streaming sims pass — EXACT R3 config (measured 91.5us @ 84% DRAM).
// grid = (ceil(L/8), B), block = 256 (8 warps), one warp per token.
// Ranking by dot * rsqrt(|t|^2) is order-equivalent to the reference cosine
// (n_i is a positive per-batch scalar; eps clamp inactive at these scales).
// ---------------------------------------------------------------------------
__global__ void __launch_bounds__(256)
sims_kernel(const float* __restrict__ i_feats,
            const float* __restrict__ image_feats,
            int L)
{
    __shared__ float4 s_i[NVEC];    // 4 KB: i_feats row for this batch

    const int b    = blockIdx.y;
    const int tid  = threadIdx.x;
    const int warp = tid >> 5;
    const int lane = tid & 31;

    s_i[tid] = reinterpret_cast<const float4*>(i_feats + (size_t)b * D_DIM)[tid];
    __syncthreads();

    const int token = blockIdx.x * 8 + warp;
    if (token >= L) return;

    const float4* __restrict__ tok = reinterpret_cast<const float4*>(
        image_feats + ((size_t)b * L + token) * D_DIM) + lane;

    float dot = 0.f, nt2 = 0.f;
    #pragma unroll
    for (int j = 0; j < NVEC / 32; ++j) {             // 8 iterations
        float4 v = __ldg(tok + j * 32);               // coalesced 128B/warp/step
        float4 a = s_i[lane + j * 32];
        dot += a.x * v.x + a.y * v.y + a.z * v.z + a.w * v.w;
        nt2 += v.x * v.x + v.y * v.y + v.z * v.z + v.w * v.w;
    }

    #pragma unroll
    for (int off = 16; off > 0; off >>= 1) {
        dot += __shfl_xor_sync(0xffffffffu, dot, off);
        nt2 += __shfl_xor_sync(0xffffffffu, nt2, off);
    }

    if (lane == 0)
        g_sims[b * L + token] = dot * rsqrtf(fmaxf(nt2, 1e-16f));
}

// ---------------------------------------------------------------------------
// Kernel T: histogram-prefiltered exact select + gather-mean. grid = B,
// block = 576 threads.
//
// Select: block min/max -> 512 linear bins -> histogram + inclusive scan ->
// cutoff bin c = first bin with cumsum >= k. Every element with rank < k has
// bin <= c, so only those ~25-50 survivors (compacted onto the first warps)
// run the exact O(L) rank loop:
//   rank(i) = #{ j : v_j < v_i || (v_j == v_i && j < i) }   (top_k-stable)
// rank < k => s_idx[rank] = i (collision-free, deterministic — identical
// result to the full rank select; degenerate range falls back to all-survivor
// which is still exact).
//
// Gather: threads 0..511; tg = tid/256 sums tokens tg, tg+2, ... over its
// 256-float4 row (12 independent coalesced loads); 2-way smem reduce; write.
// ---------------------------------------------------------------------------
__global__ void __launch_bounds__(TPB_T)
select_gather_kernel(const float* __restrict__ image_feats,
                     const int* __restrict__ k_ptr,
                     float* __restrict__ out,
                     int L)
{
    __shared__ float  s_v[MAX_L];        // sims
    __shared__ int    s_bin[MAX_L];
    __shared__ int    s_hist[NBINS];     // histogram, then inclusive cumsum
    __shared__ float  s_wmin[TPB_T / 32], s_wmax[TPB_T / 32];
    __shared__ int    s_surv[MAX_L];
    __shared__ int    s_scnt;
    __shared__ int    s_cut;
    __shared__ float  s_minv, s_inv;
    __shared__ int    s_idx[MAX_K];
    __shared__ float4 s_part[256];

    const int b    = blockIdx.x;
    const int tid  = threadIdx.x;
    const int warp = tid >> 5;
    const int lane = tid & 31;

    int k = *k_ptr;
    if (k < 1) k = 1;
    if (k > MAX_K) k = MAX_K;

    if (tid == 0) { s_scnt = 0; s_cut = NBINS - 1; }
    if (tid < NBINS) s_hist[tid] = 0;

    float v = FLT_MAX;
    float vmax = -FLT_MAX;
    if (tid < L) { v = g_sims[b * L + tid]; s_v[tid] = v; vmax = v; }

    // block min/max
    float mn = v, mx = vmax;
    #pragma unroll
    for (int off = 16; off > 0; off >>= 1) {
        mn = fminf(mn, __shfl_xor_sync(0xffffffffu, mn, off));
        mx = fmaxf(mx, __shfl_xor_sync(0xffffffffu, mx, off));
    }
    if (lane == 0) { s_wmin[warp] = mn; s_wmax[warp] = mx; }
    __syncthreads();
    if (tid == 0) {
        float m = s_wmin[0], M = s_wmax[0];
        for (int w = 1; w < TPB_T / 32; ++w) {
            m = fminf(m, s_wmin[w]);
            M = fmaxf(M, s_wmax[w]);
        }
        s_minv = m;
        float r = M - m;
        s_inv = (r > 0.f) ? ((float)NBINS / r) * (1.f - 1e-6f) : 0.f;
    }
    __syncthreads();

    // histogram
    if (tid < L) {
        int bin = (int)((v - s_minv) * s_inv);
        if (bin > NBINS - 1) bin = NBINS - 1;
        if (bin < 0) bin = 0;
        s_bin[tid] = bin;
        atomicAdd(&s_hist[bin], 1);
    }
    __syncthreads();

    // inclusive scan (Hillis-Steele, 9 steps)
    for (int off = 1; off < NBINS; off <<= 1) {
        int val = 0;
        if (tid < NBINS) {
            val = s_hist[tid];
            if (tid >= off) val += s_hist[tid - off];
        }
        __syncthreads();
        if (tid < NBINS) s_hist[tid] = val;
        __syncthreads();
    }

    // cutoff bin: first with cumsum >= k
    if (tid < NBINS) {
        int c = s_hist[tid];
        int p = tid ? s_hist[tid - 1] : 0;
        if (c >= k && p < k) s_cut = tid;
    }
    __syncthreads();

    // compact survivors (slot order may vary, result doesn't depend on it)
    if (tid < L && s_bin[tid] <= s_cut) {
        int s = atomicAdd(&s_scnt, 1);
        s_surv[s] = tid;
    }
    __syncthreads();

    // exact rank for survivors only (~25-50, handled by the first 1-2 warps)
    const int scnt = s_scnt;
    for (int t = tid; t < scnt; t += TPB_T) {
        const int i  = s_surv[t];
        const float vi = s_v[i];
        int rank = 0;
        #pragma unroll 8
        for (int j = 0; j < MAX_L; ++j) {
            float w = s_v[j];                          // LDS broadcast
            rank += (w < vi) | ((w == vi) & (j < i));
        }
        if (rank < k)
            s_idx[rank] = i;
    }
    __syncthreads();

    // gather-mean: threads 0..511; tg in {0,1}, slot in [0,256)
    const int tg   = tid >> 8;
    const int slot = tid & 255;
    float4 acc = make_float4(0.f, 0.f, 0.f, 0.f);
    if (tid < 512) {
        const float4* __restrict__ rowbase = reinterpret_cast<const float4*>(
            image_feats + (size_t)b * L * D_DIM);
        #pragma unroll 4
        for (int j = tg; j < k; j += 2) {              // 12 indep. loads each
            float4 x = __ldg(rowbase + (size_t)s_idx[j] * NVEC + slot);
            acc.x += x.x; acc.y += x.y; acc.z += x.z; acc.w += x.w;
        }
    }
    if (tid >= 256 && tid < 512)
        s_part[slot] = acc;
    __syncthreads();
    if (tid < 256) {
        float4 a1 = s_part[slot];
        const float inv_k = 1.0f / (float)k;
        float4 r;
        r.x = (acc.x + a1.x) * inv_k;
        r.y = (acc.y + a1.y) * inv_k;
        r.z = (acc.z + a1.z) * inv_k;
        r.w = (acc.w + a1.w) * inv_k;
        reinterpret_cast<float4*>(out + (size_t)b * D_DIM)[slot] = r;
    }
}

// ---------------------------------------------------------------------------
extern "C" void kernel_launch(void* const* d_in, const int* in_sizes, int n_in,
                              void* d_out, int out_size)
{
    const float* i_feats     = (const float*)d_in[0];   // [B, D]
    const float* image_feats = (const float*)d_in[1];   // [B, L, D]
    const int*   k_ptr       = (const int*)d_in[2];     // scalar k

    const int B = in_sizes[0] / D_DIM;                  // 256
    const int L = in_sizes[1] / in_sizes[0];            // 576

    dim3 gridA((L + 7) / 8, B);
    sims_kernel<<<gridA, 256>>>(i_feats, image_feats, L);

    select_gather_kernel<<<B, TPB_T>>>(image_feats, k_ptr, (float*)d_out, L);
}